// round 1
// baseline (speedup 1.0000x reference)
#include <cuda_runtime.h>
#include <cstdint>

#define Bb 8
#define Tt 2048
#define Cc 1024
#define HS 64

// scratch for Q,K,V projections (device globals: no allocation allowed)
__device__ __align__(16) float g_Q[Bb*Tt*HS];
__device__ __align__(16) float g_K[Bb*Tt*HS];
__device__ __align__(16) float g_V[Bb*Tt*HS];

typedef unsigned long long u64;

__device__ __forceinline__ u64 pack2(float lo, float hi) {
    u64 r; asm("mov.b64 %0, {%1,%2};" : "=l"(r) : "f"(lo), "f"(hi)); return r;
}
__device__ __forceinline__ void unpack2(u64 v, float& lo, float& hi) {
    asm("mov.b64 {%0,%1}, %2;" : "=f"(lo), "=f"(hi) : "l"(v));
}
__device__ __forceinline__ u64 fma2(u64 a, u64 b, u64 c) {
    u64 d; asm("fma.rn.f32x2 %0, %1, %2, %3;" : "=l"(d) : "l"(a), "l"(b), "l"(c)); return d;
}
__device__ __forceinline__ u64 mul2(u64 a, u64 b) {
    u64 d; asm("mul.rn.f32x2 %0, %1, %2;" : "=l"(d) : "l"(a), "l"(b)); return d;
}

// ---------------------------------------------------------------------------
// QKV projection: out[m, n] = sum_k x[m,k] * W[k,n], M=16384, K=1024, N=64.
// Tile 128x64, BK=16, 128 threads, thread tile 8 rows x 8 cols (packed f32x2).
// blockIdx.y selects which of Wq/Wk/Wv.
// ---------------------------------------------------------------------------
__global__ __launch_bounds__(128) void qkv_kernel(
    const float* __restrict__ x,
    const float* __restrict__ Wq,
    const float* __restrict__ Wk,
    const float* __restrict__ Wv)
{
    const int m0 = blockIdx.x * 128;
    const float* W = (blockIdx.y == 0) ? Wq : (blockIdx.y == 1) ? Wk : Wv;
    float* out = (blockIdx.y == 0) ? g_Q : (blockIdx.y == 1) ? g_K : g_V;

    __shared__ float As[16][128];   // [k][m]
    __shared__ float Bs[16][64];    // [k][n]

    const int tid = threadIdx.x;
    const int tm = tid & 15;        // 16 threads along M, 8 rows each
    const int tn = tid >> 4;        // 8 threads along N, 8 cols each

    u64 acc[8][4];
    #pragma unroll
    for (int r = 0; r < 8; r++)
        #pragma unroll
        for (int c = 0; c < 4; c++) acc[r][c] = 0ull;

    // B-load coords: thread loads 8 consecutive floats
    const int bf = tid * 8;
    const int bkk = bf >> 6;        // which k row (0..15)
    const int bn  = bf & 63;        // n offset

    for (int k0 = 0; k0 < Cc; k0 += 16) {
        // stage global loads into registers
        const float4* xp = (const float4*)(x + (size_t)(m0 + tid) * Cc + k0);
        float4 a0 = xp[0], a1 = xp[1], a2 = xp[2], a3 = xp[3];
        const float4* wp = (const float4*)(W + (size_t)(k0 + bkk) * HS + bn);
        float4 b0 = wp[0], b1 = wp[1];

        __syncthreads();  // previous compute done before overwrite
        As[ 0][tid] = a0.x; As[ 1][tid] = a0.y; As[ 2][tid] = a0.z; As[ 3][tid] = a0.w;
        As[ 4][tid] = a1.x; As[ 5][tid] = a1.y; As[ 6][tid] = a1.z; As[ 7][tid] = a1.w;
        As[ 8][tid] = a2.x; As[ 9][tid] = a2.y; As[10][tid] = a2.z; As[11][tid] = a2.w;
        As[12][tid] = a3.x; As[13][tid] = a3.y; As[14][tid] = a3.z; As[15][tid] = a3.w;
        *((float4*)&Bs[bkk][bn])     = b0;
        *((float4*)&Bs[bkk][bn + 4]) = b1;
        __syncthreads();

        #pragma unroll
        for (int kk = 0; kk < 16; kk++) {
            float4 av0 = *(const float4*)&As[kk][tm * 8];
            float4 av1 = *(const float4*)&As[kk][tm * 8 + 4];
            const u64* bp = (const u64*)&Bs[kk][tn * 8];
            u64 b2[4];
            #pragma unroll
            for (int c = 0; c < 4; c++) b2[c] = bp[c];
            float a[8] = {av0.x, av0.y, av0.z, av0.w, av1.x, av1.y, av1.z, av1.w};
            #pragma unroll
            for (int r = 0; r < 8; r++) {
                u64 ar = pack2(a[r], a[r]);
                #pragma unroll
                for (int c = 0; c < 4; c++) acc[r][c] = fma2(ar, b2[c], acc[r][c]);
            }
        }
    }

    #pragma unroll
    for (int r = 0; r < 8; r++) {
        u64* op = (u64*)(out + (size_t)(m0 + tm * 8 + r) * HS + tn * 8);
        #pragma unroll
        for (int c = 0; c < 4; c++) op[c] = acc[r][c];
    }
}

// ---------------------------------------------------------------------------
// Causal flash attention, fp32 online softmax.
// Grid: (T/64, B). 128 threads: thread t handles query row t>>1, dim-half t&1.
// K/V 64x64 tiles in smem; keys processed in chunks of 16 (keeps regs + I$ low).
// Row-blocks reversed so heavy (long causal prefix) CTAs launch first.
// ---------------------------------------------------------------------------
__global__ __launch_bounds__(128) void attn_kernel(float* __restrict__ out)
{
    const int rb = (gridDim.x - 1) - blockIdx.x;  // heavy-first
    const int b  = blockIdx.y;
    const int tid = threadIdx.x;
    const int row  = tid >> 1;          // 0..63
    const int half = tid & 1;           // which 32-dim half
    const int qrow = rb * 64 + row;

    __shared__ float Ksh[64][64];
    __shared__ float Vsh[64][64];

    // load q (scaled by 1/sqrt(C) = 1/32), packed as 16 f32x2
    const float scale = 0.03125f;
    u64 q2[16];
    {
        const float4* qp = (const float4*)(g_Q + ((size_t)b * Tt + qrow) * HS + half * 32);
        #pragma unroll
        for (int i = 0; i < 8; i++) {
            float4 v = qp[i];
            q2[2*i]   = pack2(v.x * scale, v.y * scale);
            q2[2*i+1] = pack2(v.z * scale, v.w * scale);
        }
    }

    u64 acc[16];
    #pragma unroll
    for (int i = 0; i < 16; i++) acc[i] = 0ull;
    float m = -1e30f, l = 0.0f;

    const float* Kb = g_K + (size_t)b * Tt * HS;
    const float* Vb = g_V + (size_t)b * Tt * HS;

    for (int j0 = 0; j0 <= rb * 64; j0 += 64) {
        __syncthreads();  // previous tile fully consumed
        #pragma unroll
        for (int i = 0; i < 8; i++) {
            int f = tid + i * 128;
            int r = f >> 4, c4 = (f & 15) * 4;
            *((float4*)&Ksh[r][c4]) = *(const float4*)(Kb + (size_t)(j0 + r) * HS + c4);
            *((float4*)&Vsh[r][c4]) = *(const float4*)(Vb + (size_t)(j0 + r) * HS + c4);
        }
        __syncthreads();

        #pragma unroll 1
        for (int jc = 0; jc < 64; jc += 16) {
            // ---- scores for 16 keys ----
            float s[16];
            float tmax = -1e30f;
            #pragma unroll
            for (int j = 0; j < 16; j++) {
                const u64* kp = (const u64*)&Ksh[jc + j][half * 32];
                u64 sp = 0ull;
                #pragma unroll
                for (int d = 0; d < 16; d++) sp = fma2(q2[d], kp[d], sp);
                float lo, hi; unpack2(sp, lo, hi);
                float sv = lo + hi;
                sv += __shfl_xor_sync(0xffffffffu, sv, 1);   // add other half
                if (j0 + jc + j > qrow) sv = -1e30f;          // causal mask
                s[j] = sv;
                tmax = fmaxf(tmax, sv);
            }
            // ---- online softmax update ----
            float m_new = fmaxf(m, tmax);
            float corr = __expf(m - m_new);
            l *= corr;
            u64 c2 = pack2(corr, corr);
            #pragma unroll
            for (int i = 0; i < 16; i++) acc[i] = mul2(acc[i], c2);
            #pragma unroll
            for (int j = 0; j < 16; j++) {
                float p = __expf(s[j] - m_new);
                l += p;
                u64 p2 = pack2(p, p);
                const u64* vp = (const u64*)&Vsh[jc + j][half * 32];
                #pragma unroll
                for (int d = 0; d < 16; d++) acc[d] = fma2(p2, vp[d], acc[d]);
            }
            m = m_new;
        }
    }

    float rl = 1.0f / l;
    u64 r2 = pack2(rl, rl);
    float* op = out + ((size_t)b * Tt + qrow) * HS + half * 32;
    #pragma unroll
    for (int i = 0; i < 16; i++) *(u64*)(op + 2 * i) = mul2(acc[i], r2);
}

extern "C" void kernel_launch(void* const* d_in, const int* in_sizes, int n_in,
                              void* d_out, int out_size)
{
    const float* x  = (const float*)d_in[0];
    const float* Wq = (const float*)d_in[1];
    const float* Wk = (const float*)d_in[2];
    const float* Wv = (const float*)d_in[3];
    float* out = (float*)d_out;

    dim3 g1((Bb * Tt) / 128, 3);
    qkv_kernel<<<g1, 128>>>(x, Wq, Wk, Wv);

    dim3 g2(Tt / 64, Bb);
    attn_kernel<<<g2, 128>>>(out);
}